// round 1
// baseline (speedup 1.0000x reference)
#include <cuda_runtime.h>
#include <math.h>

#define NUM_FEATURES 10
#define EMBED 256
#define MAXLEN 366
#define PE_ROWS (MAXLEN + 1)
#define OUT_DIM (2 * EMBED)

// Positional-encoding table: row 0 = zeros, rows 1..366 = sin/cos for positions 0..365.
__device__ float g_pe[PE_ROWS * EMBED];

// ---------------------------------------------------------------------------
// Init kernel: fill the PE table. One thread per (row, sin/cos pair).
// Done in double precision so we track the numpy float32 reference to ~1e-7.
// Cost: ~47K threads of FP64 sincos -> ~2 us, negligible vs. the 268MB write.
// ---------------------------------------------------------------------------
__global__ void fill_pe_kernel() {
    int idx = blockIdx.x * blockDim.x + threadIdx.x;   // pair index
    const int pairs_per_row = EMBED / 2;
    const int total = PE_ROWS * pairs_per_row;
    if (idx >= total) return;
    int row = idx / pairs_per_row;
    int i   = idx - row * pairs_per_row;               // 0..127
    if (row == 0) {
        g_pe[2 * i]     = 0.0f;
        g_pe[2 * i + 1] = 0.0f;
    } else {
        double p   = (double)(row - 1);
        double div = exp((double)(2 * i) * (-log(10000.0) / (double)EMBED));
        double a   = p * div;
        g_pe[row * EMBED + 2 * i]     = (float)sin(a);
        g_pe[row * EMBED + 2 * i + 1] = (float)cos(a);
    }
}

// ---------------------------------------------------------------------------
// Main kernel.
// blockDim = 256: threadIdx = (token_lane[0..3] << 6) | e_lane[0..63].
// Each thread owns 4 consecutive embed channels (e0 = e_lane*4) and keeps its
// W[4][10] slice + bias in registers across a grid-stride token loop.
// Per token: 10 warp-broadcast x loads, 40 FFMA, one float4 PE gather
// (L2-resident table), two float4 coalesced stores.
// ---------------------------------------------------------------------------
__global__ void bert_embed_kernel(const float* __restrict__ x,    // [ntok, 10]
                                  const int*   __restrict__ doy,  // [ntok]
                                  const float* __restrict__ W,    // [256, 10]
                                  const float* __restrict__ bias_g,// [256]
                                  float*       __restrict__ out,  // [ntok, 512]
                                  int ntok) {
    const int e_lane = threadIdx.x & 63;
    const int t_lane = threadIdx.x >> 6;
    const int e0 = e_lane * 4;

    // Load this thread's W slice + bias into registers (once per block).
    float w[4][NUM_FEATURES];
    float bias[4];
#pragma unroll
    for (int r = 0; r < 4; r++) {
        bias[r] = __ldg(bias_g + e0 + r);
#pragma unroll
        for (int f = 0; f < NUM_FEATURES; f++)
            w[r][f] = __ldg(W + (e0 + r) * NUM_FEATURES + f);
    }

    const int stride = gridDim.x * 4;
    for (int t = blockIdx.x * 4 + t_lane; t < ntok; t += stride) {
        const float* xp = x + (size_t)t * NUM_FEATURES;

        float a0 = bias[0], a1 = bias[1], a2 = bias[2], a3 = bias[3];
#pragma unroll
        for (int f = 0; f < NUM_FEATURES; f++) {
            float xv = __ldg(xp + f);          // warp-uniform -> broadcast
            a0 = fmaf(xv, w[0][f], a0);
            a1 = fmaf(xv, w[1][f], a1);
            a2 = fmaf(xv, w[2][f], a2);
            a3 = fmaf(xv, w[3][f], a3);
        }

        int d = __ldg(doy + t);                // 0..366
        float4 pev = *reinterpret_cast<const float4*>(&g_pe[d * EMBED + e0]);

        float* op = out + (size_t)t * OUT_DIM;
        *reinterpret_cast<float4*>(op + e0)         = make_float4(a0, a1, a2, a3);
        *reinterpret_cast<float4*>(op + EMBED + e0) = pev;
    }
}

extern "C" void kernel_launch(void* const* d_in, const int* in_sizes, int n_in,
                              void* d_out, int out_size) {
    const float* x    = (const float*)d_in[0];   // input_sequence [256,512,10]
    const int*   doy  = (const int*)  d_in[1];   // doy_sequence   [256,512]
    const float* W    = (const float*)d_in[2];   // [256,10]
    const float* b    = (const float*)d_in[3];   // [256]
    float*       out  = (float*)d_out;           // [256,512,512]

    const int ntok = in_sizes[1];                // 131072 tokens

    const int pe_threads = PE_ROWS * (EMBED / 2);
    fill_pe_kernel<<<(pe_threads + 255) / 256, 256>>>();

    // 592 blocks ~= 4 resident blocks per SM on 148 SMs; grid-stride loop
    // amortizes the per-block W register load over ~55 tokens per lane.
    bert_embed_kernel<<<592, 256>>>(x, doy, W, b, out, ntok);
}

// round 2
// speedup vs baseline: 1.9668x; 1.9668x over previous
#include <cuda_runtime.h>
#include <math.h>

#define NUM_FEATURES 10
#define EMBED 256
#define MAXLEN 366
#define PE_ROWS (MAXLEN + 1)
#define OUT_DIM (2 * EMBED)
#define MAX_TOK_PER_BLOCK 224   // ceil(131072/592)=222, rounded up

// Positional-encoding table: row 0 = zeros, rows 1..366 = sin/cos for positions 0..365.
__device__ float g_pe[PE_ROWS * EMBED];

// ---------------------------------------------------------------------------
// Fill PE table in single precision (fast MUFU path). Max abs error vs the
// float32 numpy reference ~5e-5 -- far below the 1e-3 rel-err gate, and ~10x
// cheaper than the FP64 software-transcendental version (18.7us -> ~2us).
// ---------------------------------------------------------------------------
__global__ void fill_pe_kernel() {
    int idx = blockIdx.x * blockDim.x + threadIdx.x;   // (row, pair) index
    const int pairs = EMBED / 2;
    if (idx >= PE_ROWS * pairs) return;
    int row = idx / pairs;
    int i   = idx - row * pairs;                       // 0..127
    float s = 0.0f, c = 0.0f;
    if (row > 0) {
        const float k = -(logf(10000.0f) / (float)EMBED);
        float div = expf((float)(2 * i) * k);
        float a   = (float)(row - 1) * div;
        sincosf(a, &s, &c);
    }
    g_pe[row * EMBED + 2 * i]     = s;
    g_pe[row * EMBED + 2 * i + 1] = c;
}

// ---------------------------------------------------------------------------
// Main kernel.
// Each block owns a CONTIGUOUS token range. x and doy for the range are staged
// once through shared memory (coalesced), so inner-loop x reads are broadcast
// LDS (bank-conflict-free, warp-uniform address).
//
// Thread mapping: e_lane = tid & 127 owns 2 consecutive embed channels
// (w[2][10] in regs); t_lane = tid >> 7 in {0,1}. Two tokens are processed
// per iteration for MLP (2 independent PE gathers + 4 streaming stores in
// flight). ~48 regs -> 5 blocks/SM; grid 592 = one full resident wave.
// ---------------------------------------------------------------------------
struct WReg { float w[2][NUM_FEATURES]; float b0, b1; };

__device__ __forceinline__ void do_token(int tglob, int ttloc,
                                         const float* __restrict__ sx,
                                         const int*   __restrict__ sdoy,
                                         const WReg& wr, int e0,
                                         float* __restrict__ out) {
    const float* xp = sx + ttloc * NUM_FEATURES;       // warp-uniform address
    float a0 = wr.b0, a1 = wr.b1;
#pragma unroll
    for (int f = 0; f < NUM_FEATURES; f++) {
        float xv = xp[f];                              // LDS broadcast
        a0 = fmaf(xv, wr.w[0][f], a0);
        a1 = fmaf(xv, wr.w[1][f], a1);
    }
    int d = sdoy[ttloc];
    float2 pev = *reinterpret_cast<const float2*>(&g_pe[d * EMBED + e0]);

    float* op = out + (size_t)tglob * OUT_DIM;
    __stcs(reinterpret_cast<float2*>(op + e0),         make_float2(a0, a1));
    __stcs(reinterpret_cast<float2*>(op + EMBED + e0), pev);
}

__global__ __launch_bounds__(256, 5)
void bert_embed_kernel(const float* __restrict__ x,     // [ntok, 10]
                       const int*   __restrict__ doy,   // [ntok]
                       const float* __restrict__ W,     // [256, 10]
                       const float* __restrict__ bias_g,// [256]
                       float*       __restrict__ out,   // [ntok, 512]
                       int ntok) {
    __shared__ float sx[MAX_TOK_PER_BLOCK * NUM_FEATURES];
    __shared__ int   sdoy[MAX_TOK_PER_BLOCK];

    const int per = (ntok + gridDim.x - 1) / gridDim.x;
    const int t0  = blockIdx.x * per;
    const int cnt = min(per, ntok - t0);
    if (cnt <= 0) return;

    // Stage x + doy for this block's token range (coalesced global reads).
    for (int i = threadIdx.x; i < cnt * NUM_FEATURES; i += blockDim.x)
        sx[i] = __ldg(x + (size_t)t0 * NUM_FEATURES + i);
    for (int i = threadIdx.x; i < cnt; i += blockDim.x)
        sdoy[i] = __ldg(doy + t0 + i);

    const int e_lane = threadIdx.x & 127;
    const int t_lane = threadIdx.x >> 7;               // 0 or 1
    const int e0 = e_lane * 2;

    // This thread's 2-row weight slice + bias in registers.
    WReg wr;
#pragma unroll
    for (int r = 0; r < 2; r++)
#pragma unroll
        for (int f = 0; f < NUM_FEATURES; f++)
            wr.w[r][f] = __ldg(W + (e0 + r) * NUM_FEATURES + f);
    wr.b0 = __ldg(bias_g + e0);
    wr.b1 = __ldg(bias_g + e0 + 1);

    __syncthreads();

    int tt = t_lane;
    // Unroll-by-2: two independent tokens in flight per thread.
    for (; tt + 2 < cnt; tt += 4) {
        do_token(t0 + tt,     tt,     sx, sdoy, wr, e0, out);
        do_token(t0 + tt + 2, tt + 2, sx, sdoy, wr, e0, out);
    }
    for (; tt < cnt; tt += 2)
        do_token(t0 + tt, tt, sx, sdoy, wr, e0, out);
}

extern "C" void kernel_launch(void* const* d_in, const int* in_sizes, int n_in,
                              void* d_out, int out_size) {
    const float* x    = (const float*)d_in[0];   // input_sequence [256,512,10]
    const int*   doy  = (const int*)  d_in[1];   // doy_sequence   [256,512]
    const float* W    = (const float*)d_in[2];   // [256,10]
    const float* b    = (const float*)d_in[3];   // [256]
    float*       out  = (float*)d_out;           // [256,512,512]

    const int ntok = in_sizes[1];                // 131072 tokens

    const int pe_threads = PE_ROWS * (EMBED / 2);
    fill_pe_kernel<<<(pe_threads + 255) / 256, 256>>>();

    bert_embed_kernel<<<592, 256>>>(x, doy, W, b, out, ntok);
}